// round 14
// baseline (speedup 1.0000x reference)
#include <cuda_runtime.h>
#include <cuda_bf16.h>
#include <cuda_fp16.h>
#include <math.h>
#include <stdint.h>

// Problem constants
#define BATCH   2
#define SEQ     2048
#define DMODEL  2048
#define NHEADS  16
#define DHEAD   128
#define MROWS   (BATCH*SEQ)          // 4096
#define QKVDIM  (3*DMODEL)           // 6144
#define KDIM    2048

// Scratch (__device__ globals; allocation-free rule)
__device__ float2 g_rope[(size_t)SEQ * 64];
__device__ __half g_x16[(size_t)MROWS * KDIM];
__device__ __half g_wq16[(size_t)QKVDIM * KDIM];
__device__ __half g_a16[(size_t)MROWS * DMODEL];
__device__ __half g_wo16[(size_t)DMODEL * KDIM];
// fp16 attention operands, [B][H][T][D]
#define NATT ((size_t)BATCH * NHEADS * SEQ * DHEAD)
__device__ __half g_qh16[NATT], g_ql16[NATT];
__device__ __half g_kh16[NATT];
__device__ __half g_vh16[NATT];

// ---------------------------------------------------------------------------
// PTX helpers
// ---------------------------------------------------------------------------
static __device__ __forceinline__ uint32_t smem_u32(const void* p) {
    uint32_t a;
    asm("{ .reg .u64 t; cvta.to.shared.u64 t, %1; cvt.u32.u64 %0, t; }" : "=r"(a) : "l"(p));
    return a;
}
static __device__ __forceinline__ void cpasync16(uint32_t dst, const void* src) {
    asm volatile("cp.async.cg.shared.global [%0], [%1], 16;\n" :: "r"(dst), "l"(src));
}
#define CP_COMMIT() asm volatile("cp.async.commit_group;\n" ::: "memory")
#define CP_WAIT0()  asm volatile("cp.async.wait_group 0;\n" ::: "memory")
#define CP_WAIT1()  asm volatile("cp.async.wait_group 1;\n" ::: "memory")

static __device__ __forceinline__ void ldsm_x4(uint32_t& r0, uint32_t& r1,
                                               uint32_t& r2, uint32_t& r3, uint32_t a) {
    asm volatile("ldmatrix.sync.aligned.m8n8.x4.shared.b16 {%0,%1,%2,%3}, [%4];"
                 : "=r"(r0), "=r"(r1), "=r"(r2), "=r"(r3) : "r"(a));
}
static __device__ __forceinline__ void ldsm_x4t(uint32_t& r0, uint32_t& r1,
                                                uint32_t& r2, uint32_t& r3, uint32_t a) {
    asm volatile("ldmatrix.sync.aligned.m8n8.x4.trans.shared.b16 {%0,%1,%2,%3}, [%4];"
                 : "=r"(r0), "=r"(r1), "=r"(r2), "=r"(r3) : "r"(a));
}
static __device__ __forceinline__ void mma_f16(float* c, const uint32_t* a,
                                               uint32_t b0, uint32_t b1) {
    asm volatile(
        "mma.sync.aligned.m16n8k16.row.col.f32.f16.f16.f32 "
        "{%0,%1,%2,%3}, {%4,%5,%6,%7}, {%8,%9}, {%0,%1,%2,%3};"
        : "+f"(c[0]), "+f"(c[1]), "+f"(c[2]), "+f"(c[3])
        : "r"(a[0]), "r"(a[1]), "r"(a[2]), "r"(a[3]), "r"(b0), "r"(b1));
}
static __device__ __forceinline__ void pack_hl(float f0, float f1, uint32_t& hi, uint32_t& lo) {
    __half2 h = __floats2half2_rn(f0, f1);
    float2 fb = __half22float2(h);
    __half2 l2 = __floats2half2_rn(f0 - fb.x, f1 - fb.y);
    hi = *reinterpret_cast<uint32_t*>(&h);
    lo = *reinterpret_cast<uint32_t*>(&l2);
}
static __device__ __forceinline__ uint32_t ex2_f16x2(float a, float b) {
    uint32_t d;
    asm("{ .reg .b32 t;\n cvt.rn.f16x2.f32 t, %2, %1;\n ex2.approx.f16x2 %0, t;\n}"
        : "=r"(d) : "f"(a), "f"(b));
    return d;
}

// ---------------------------------------------------------------------------
// Merged fp32 -> fp16 conversion for x, Wqkv, WO (one launch)
// ---------------------------------------------------------------------------
#define N4_X  ((MROWS * KDIM) / 4)       // 2097152
#define N4_WQ ((QKVDIM * KDIM) / 4)      // 3145728
#define N4_WO ((DMODEL * KDIM) / 4)      // 1048576
#define N4_ALL (N4_X + N4_WQ + N4_WO)    // 6291456

__global__ __launch_bounds__(256) void cvt_all_kernel(
    const float4* __restrict__ x,  uint2* __restrict__ x16,
    const float4* __restrict__ wq, uint2* __restrict__ wq16,
    const float4* __restrict__ wo, uint2* __restrict__ wo16)
{
    int idx = blockIdx.x * 256 + threadIdx.x;
    const float4* s;
    uint2* d;
    int i;
    if (idx < N4_X)              { s = x;  d = x16;  i = idx; }
    else if (idx < N4_X + N4_WQ) { s = wq; d = wq16; i = idx - N4_X; }
    else                         { s = wo; d = wo16; i = idx - N4_X - N4_WQ; }
    float4 v = s[i];
    __half2 h01 = __floats2half2_rn(v.x, v.y);
    __half2 h23 = __floats2half2_rn(v.z, v.w);
    uint2 dv;
    dv.x = *reinterpret_cast<uint32_t*>(&h01); dv.y = *reinterpret_cast<uint32_t*>(&h23);
    d[i] = dv;
}

// ---------------------------------------------------------------------------
// RoPE cos/sin table
// ---------------------------------------------------------------------------
__global__ __launch_bounds__(256) void rope_table_kernel(float2* __restrict__ tab)
{
    int idx = blockIdx.x * 256 + threadIdx.x;
    int i = idx & 63, t = idx >> 6;
    double freq = exp(-9.210340371976184 * (double)(2 * i) / 128.0);
    double sd, cd;
    sincos((double)t * freq, &sd, &cd);
    tab[idx] = make_float2((float)cd, (float)sd);
}

// ---------------------------------------------------------------------------
// GEMM mainloop (NT, fp16: C = A * B^T), BK=64 double-buffered, occ 2.
// BM=BN=128, 256 threads, 8 warps (2m x 4n), warp tile 64x32.
// ---------------------------------------------------------------------------
#define BM 128
#define BN 128
#define BK 64
#define SROW 72
#define PART_BYTES (128 * SROW * 2)          // 18432
#define A_OFF 0
#define B_OFF PART_BYTES
#define STG_BYTES (2 * PART_BYTES)           // 36864
#define GSMEM (2 * STG_BYTES)                // 73728

static __device__ __forceinline__ void g_load_stage(
    uint32_t sb, int buf, int s, int bm, int bn, int tid,
    const __half* __restrict__ A, const __half* __restrict__ B)
{
    uint32_t base = sb + buf * STG_BYTES;
    const int k0 = s * BK;
#pragma unroll
    for (int it = 0; it < 8; it++) {
        int idx = tid + it * 256;
        int part = idx >> 10;
        int rem = idx & 1023;
        int r = rem >> 3, ch = rem & 7;
        const __half* src = part ? B : A;
        int row = part ? (bn + r) : (bm + r);
        cpasync16(base + part * PART_BYTES + r * (SROW * 2) + ch * 16,
                  src + (size_t)row * KDIM + k0 + ch * 8);
    }
    CP_COMMIT();
}

static __device__ __forceinline__ void g_mainloop(
    uint32_t sb, int bm, int bn, int tid, int lane, int wm, int wn,
    const __half* __restrict__ A, const __half* __restrict__ B,
    float acc[4][4][4])
{
    const uint32_t aRow = wm * 64 + (lane & 15);
    const uint32_t aCol = (lane >> 4) << 3;
    const uint32_t bOff = (wn * 32 + (lane & 7) + ((lane & 16) >> 1)) * (SROW * 2)
                        + (((lane >> 3) & 1) << 3) * 2;

    g_load_stage(sb, 0, 0, bm, bn, tid, A, B);

    const int NS = KDIM / BK;                // 32
    for (int s = 0; s < NS; s++) {
        const int buf = s & 1;
        if (s + 1 < NS) {
            g_load_stage(sb, buf ^ 1, s + 1, bm, bn, tid, A, B);
            CP_WAIT1();
        } else {
            CP_WAIT0();
        }
        __syncthreads();

        uint32_t base = sb + buf * STG_BYTES;
#pragma unroll
        for (int kk = 0; kk < BK; kk += 16) {
            uint32_t af[4][4], bf[4][2];
#pragma unroll
            for (int mt = 0; mt < 4; mt++)
                ldsm_x4(af[mt][0], af[mt][1], af[mt][2], af[mt][3],
                        base + A_OFF + (aRow + mt * 16) * (SROW * 2) + (aCol + kk) * 2);
#pragma unroll
            for (int np = 0; np < 2; np++)
                ldsm_x4(bf[2*np][0], bf[2*np][1], bf[2*np+1][0], bf[2*np+1][1],
                        base + B_OFF + bOff + np * 16 * (SROW * 2) + kk * 2);
#pragma unroll
            for (int mt = 0; mt < 4; mt++)
#pragma unroll
                for (int nt = 0; nt < 4; nt++)
                    mma_f16(acc[mt][nt], af[mt], bf[nt][0], bf[nt][1]);
        }
        __syncthreads();
    }
}

// Plain fp32-output GEMM (WO projection)
__global__ __launch_bounds__(256, 2) void gemm_mma(
    const __half* __restrict__ A, const __half* __restrict__ B,
    float* __restrict__ C, int ldc)
{
    extern __shared__ char smem[];
    uint32_t sb = smem_u32(smem);
    const int tid = threadIdx.x, wid = tid >> 5, lane = tid & 31;
    const int wm = wid >> 2, wn = wid & 3;
    const int bm = blockIdx.y * BM, bn = blockIdx.x * BN;

    float acc[4][4][4];
#pragma unroll
    for (int i = 0; i < 4; i++)
#pragma unroll
        for (int j = 0; j < 4; j++)
#pragma unroll
            for (int e = 0; e < 4; e++) acc[i][j][e] = 0.f;

    g_mainloop(sb, bm, bn, tid, lane, wm, wn, A, B, acc);

    const int r0 = bm + wm * 64 + (lane >> 2);
    const int c0 = bn + wn * 32 + 2 * (lane & 3);
#pragma unroll
    for (int mt = 0; mt < 4; mt++)
#pragma unroll
        for (int nt = 0; nt < 4; nt++) {
            float2 v0 = make_float2(acc[mt][nt][0], acc[mt][nt][1]);
            float2 v1 = make_float2(acc[mt][nt][2], acc[mt][nt][3]);
            *reinterpret_cast<float2*>(&C[(size_t)(r0 + mt * 16)     * ldc + c0 + nt * 8]) = v0;
            *reinterpret_cast<float2*>(&C[(size_t)(r0 + mt * 16 + 8) * ldc + c0 + nt * 8]) = v1;
        }
}

// QKV GEMM with fused RoPE + fp16 pack + [B,H,T,D] transpose epilogue.
__global__ __launch_bounds__(256, 2) void gemm_qkv(
    const __half* __restrict__ A, const __half* __restrict__ B,
    const float2* __restrict__ tab,
    __half* __restrict__ Qh, __half* __restrict__ Ql,
    __half* __restrict__ Kh, __half* __restrict__ Vh)
{
    extern __shared__ char smem[];
    uint32_t sb = smem_u32(smem);
    const int tid = threadIdx.x, wid = tid >> 5, lane = tid & 31;
    const int wm = wid >> 2, wn = wid & 3;
    const int bm = blockIdx.y * BM, bn = blockIdx.x * BN;

    float acc[4][4][4];
#pragma unroll
    for (int i = 0; i < 4; i++)
#pragma unroll
        for (int j = 0; j < 4; j++)
#pragma unroll
            for (int e = 0; e < 4; e++) acc[i][j][e] = 0.f;

    g_mainloop(sb, bm, bn, tid, lane, wm, wn, A, B, acc);

    const int mat  = bn >> 11;                  // 0=Q,1=K,2=V
    const int head = (bn >> 7) & (NHEADS - 1);
    const float QSCL = 0.1275174456f;           // log2(e)/sqrt(128)

    const int r0 = bm + wm * 64 + (lane >> 2);
    const int c0 = (bn & 127) + wn * 32 + 2 * (lane & 3);
    const int b  = r0 >> 11;
    const size_t obase = ((size_t)(b * NHEADS + head)) * SEQ * DHEAD;

#pragma unroll
    for (int mt = 0; mt < 4; mt++) {
        const int tA = (r0 + mt * 16) & (SEQ - 1);
        const int tB = tA + 8;
#pragma unroll
        for (int nt = 0; nt < 4; nt++) {
            const int d = c0 + nt * 8;
            float x0 = acc[mt][nt][0], x1 = acc[mt][nt][1];
            float y0 = acc[mt][nt][2], y1 = acc[mt][nt][3];
            if (mat < 2) {
                float2 csA = tab[tA * 64 + (d >> 1)];
                float2 csB = tab[tB * 64 + (d >> 1)];
                float nx0 = x0 * csA.x - x1 * csA.y;
                float nx1 = x1 * csA.x + x0 * csA.y;
                float ny0 = y0 * csB.x - y1 * csB.y;
                float ny1 = y1 * csB.x + y0 * csB.y;
                x0 = nx0; x1 = nx1; y0 = ny0; y1 = ny1;
                if (mat == 0) { x0 *= QSCL; x1 *= QSCL; y0 *= QSCL; y1 *= QSCL; }
            }
            size_t dA = obase + (size_t)tA * DHEAD + d;
            size_t dB = obase + (size_t)tB * DHEAD + d;
            if (mat == 0) {
                uint32_t hi, lo;
                pack_hl(x0, x1, hi, lo);
                *reinterpret_cast<uint32_t*>(Qh + dA) = hi;
                *reinterpret_cast<uint32_t*>(Ql + dA) = lo;
                pack_hl(y0, y1, hi, lo);
                *reinterpret_cast<uint32_t*>(Qh + dB) = hi;
                *reinterpret_cast<uint32_t*>(Ql + dB) = lo;
            } else {
                __half* D = (mat == 1) ? Kh : Vh;
                __half2 v0 = __floats2half2_rn(x0, x1);
                __half2 v1 = __floats2half2_rn(y0, y1);
                *reinterpret_cast<__half2*>(D + dA) = v0;
                *reinterpret_cast<__half2*>(D + dB) = v1;
            }
        }
    }
}

// ---------------------------------------------------------------------------
// Flash attention. Q direct global->registers. KV double-buffered in 128-key
// SUPER-TILES (2x 64-key sub-tiles per barrier pair). TQ=128, 8 warps.
// ---------------------------------------------------------------------------
#define AT_SROWB 272
#define KPART 34816                  // 128 rows x 272B (per matrix per buffer)
#define SM_K  0                      // 2 bufs
#define SM_V  69632                  // 2 bufs
#define AT_SMEM 139264

// Load one 128-key super-tile (K + V) into buffer buf.
static __device__ __forceinline__ void at_load_kv(
    uint32_t sb, int buf, int st, size_t bh, int tid,
    const __half* __restrict__ Kh, const __half* __restrict__ Vh)
{
    const int k0 = st * 128;
#pragma unroll
    for (int it = 0; it < 16; it++) {
        int idx = tid + it * 256;           // 0..4095
        int part = idx >> 11;               // 0:Kh 1:Vh
        int rem = idx & 2047;
        int r = rem >> 4, ch = rem & 15;    // r 0..127
        const __half* src = (part == 0) ? Kh : Vh;
        uint32_t dbase = ((part == 0) ? SM_K : SM_V) + buf * KPART;
        cpasync16(sb + dbase + r * AT_SROWB + ch * 16,
                  src + ((size_t)(bh + k0 + r)) * DHEAD + ch * 8);
    }
    CP_COMMIT();
}

__global__ __launch_bounds__(256, 1) void attn_mma(
    const __half* __restrict__ Qh, const __half* __restrict__ Ql,
    const __half* __restrict__ Kh, const __half* __restrict__ Vh,
    __half* __restrict__ O16)
{
    extern __shared__ char smem[];
    uint32_t sb = smem_u32(smem);
    const int tid = threadIdx.x, lane = tid & 31, w = tid >> 5;
    const int qt = gridDim.x - 1 - blockIdx.x;
    const int h = blockIdx.y, b = blockIdx.z;
    const int q0 = qt * 128;
    const size_t bh = (size_t)(b * NHEADS + h) * SEQ;

    at_load_kv(sb, 0, 0, bh, tid, Kh, Vh);

    // Q fragments straight from global into registers.
    uint32_t qhf[8][4], qlf[8][4];
    {
        const size_t rowbase = (bh + q0 + w * 16 + (lane >> 2)) * (size_t)DHEAD
                             + 2 * (lane & 3);
        const __half* ph = Qh + rowbase;
        const __half* pl = Ql + rowbase;
#pragma unroll
        for (int ks = 0; ks < 8; ks++) {
            int c = ks * 16;
            qhf[ks][0] = *reinterpret_cast<const uint32_t*>(ph + c);
            qhf[ks][1] = *reinterpret_cast<const uint32_t*>(ph + 8 * DHEAD + c);
            qhf[ks][2] = *reinterpret_cast<const uint32_t*>(ph + c + 8);
            qhf[ks][3] = *reinterpret_cast<const uint32_t*>(ph + 8 * DHEAD + c + 8);
            qlf[ks][0] = *reinterpret_cast<const uint32_t*>(pl + c);
            qlf[ks][1] = *reinterpret_cast<const uint32_t*>(pl + 8 * DHEAD + c);
            qlf[ks][2] = *reinterpret_cast<const uint32_t*>(pl + c + 8);
            qlf[ks][3] = *reinterpret_cast<const uint32_t*>(pl + 8 * DHEAD + c + 8);
        }
    }

    float m[2] = {-1e30f, -1e30f}, l[2] = {0.f, 0.f};
    float O[16][4];
#pragma unroll
    for (int i = 0; i < 16; i++)
#pragma unroll
        for (int e = 0; e < 4; e++) O[i][e] = 0.f;

    const uint32_t koff = ((lane & 7) + ((lane & 16) >> 1)) * AT_SROWB + (((lane >> 3) & 1) << 3) * 2;
    const uint32_t voff = (lane & 15) * AT_SROWB + (((uint32_t)lane >> 4) << 3) * 2;
    const uint32_t ONES = 0x3C003C00u;

    const int nst = qt + 1;                  // 128-key super-tiles
    for (int st = 0; st < nst; st++) {
        const int buf = st & 1;
        __syncthreads();
        if (st + 1 < nst) {
            at_load_kv(sb, buf ^ 1, st + 1, bh, tid, Kh, Vh);
            CP_WAIT1();
        } else {
            CP_WAIT0();
        }
        __syncthreads();

#pragma unroll
        for (int sub = 0; sub < 2; sub++) {
            const int k0 = st * 128 + sub * 64;
            const uint32_t subOff = (uint32_t)(sub * 64) * AT_SROWB;

            // ---- S = Q K^T (2-term: Qh*Kh + Ql*Kh), Q from registers ----
            float sacc[8][4];
#pragma unroll
            for (int nt = 0; nt < 8; nt++)
#pragma unroll
                for (int e = 0; e < 4; e++) sacc[nt][e] = 0.f;

            const uint32_t kbase = sb + SM_K + buf * KPART + subOff;
#pragma unroll
            for (int ks = 0; ks < 8; ks++) {
#pragma unroll
                for (int np = 0; np < 4; np++) {
                    uint32_t k0r, k1r, k2r, k3r;
                    ldsm_x4(k0r, k1r, k2r, k3r,
                            kbase + koff + np * 16 * AT_SROWB + ks * 32);
                    mma_f16(sacc[2*np],   qhf[ks], k0r, k1r);
                    mma_f16(sacc[2*np],   qlf[ks], k0r, k1r);
                    mma_f16(sacc[2*np+1], qhf[ks], k2r, k3r);
                    mma_f16(sacc[2*np+1], qlf[ks], k2r, k3r);
                }
            }

            // ---- causal mask (diagonal tiles only) ----
            if (k0 + 63 > q0 + w * 16) {
                const int rA = q0 + w * 16 + (lane >> 2);
#pragma unroll
                for (int nt = 0; nt < 8; nt++) {
                    int c = k0 + nt * 8 + 2 * (lane & 3);
                    if (c     > rA)     sacc[nt][0] = -1e30f;
                    if (c + 1 > rA)     sacc[nt][1] = -1e30f;
                    if (c     > rA + 8) sacc[nt][2] = -1e30f;
                    if (c + 1 > rA + 8) sacc[nt][3] = -1e30f;
                }
            }

            // ---- online softmax (log2 units) ----
            float mx0 = sacc[0][0], mx1 = sacc[0][2];
#pragma unroll
            for (int nt = 0; nt < 8; nt++) {
                mx0 = fmaxf(mx0, fmaxf(sacc[nt][0], sacc[nt][1]));
                mx1 = fmaxf(mx1, fmaxf(sacc[nt][2], sacc[nt][3]));
            }
            mx0 = fmaxf(mx0, __shfl_xor_sync(0xffffffffu, mx0, 1));
            mx0 = fmaxf(mx0, __shfl_xor_sync(0xffffffffu, mx0, 2));
            mx1 = fmaxf(mx1, __shfl_xor_sync(0xffffffffu, mx1, 1));
            mx1 = fmaxf(mx1, __shfl_xor_sync(0xffffffffu, mx1, 2));
            const float mn0 = fmaxf(m[0], mx0), mn1 = fmaxf(m[1], mx1);
            const float fac0 = exp2f(m[0] - mn0), fac1 = exp2f(m[1] - mn1);
            m[0] = mn0; m[1] = mn1;

            // ---- P = 2^(s - mn) as fp16 A-fragments ----
            uint32_t aPh[4][4];
#pragma unroll
            for (int ks = 0; ks < 4; ks++) {
                aPh[ks][0] = ex2_f16x2(sacc[2*ks][0]   - mn0, sacc[2*ks][1]   - mn0);
                aPh[ks][1] = ex2_f16x2(sacc[2*ks][2]   - mn1, sacc[2*ks][3]   - mn1);
                aPh[ks][2] = ex2_f16x2(sacc[2*ks+1][0] - mn0, sacc[2*ks+1][1] - mn0);
                aPh[ks][3] = ex2_f16x2(sacc[2*ks+1][2] - mn1, sacc[2*ks+1][3] - mn1);
            }

            // ---- rescale O; O += P Vh; l via ones-mma ----
#pragma unroll
            for (int i = 0; i < 16; i++) {
                O[i][0] *= fac0; O[i][1] *= fac0;
                O[i][2] *= fac1; O[i][3] *= fac1;
            }
            float Olsum[4] = {0.f, 0.f, 0.f, 0.f};
            const uint32_t vbase = sb + SM_V + buf * KPART + subOff;
#pragma unroll
            for (int ks = 0; ks < 4; ks++) {
                mma_f16(Olsum, aPh[ks], ONES, ONES);
#pragma unroll
                for (int dt = 0; dt < 8; dt++) {
                    uint32_t va = vbase + voff + ks * 16 * AT_SROWB + dt * 32;
                    uint32_t vh0, vh1, vh2, vh3;
                    ldsm_x4t(vh0, vh1, vh2, vh3, va);
                    mma_f16(O[2*dt],   aPh[ks], vh0, vh1);
                    mma_f16(O[2*dt+1], aPh[ks], vh2, vh3);
                }
            }
            l[0] = l[0] * fac0 + Olsum[0];
            l[1] = l[1] * fac1 + Olsum[2];
        }
    }

    // ---- normalize & write fp16 to [b, t, h*128+d] ----
    const float inv0 = 1.f / l[0], inv1 = 1.f / l[1];
    const int rowA = q0 + w * 16 + (lane >> 2);
    const size_t baseA = ((size_t)b * SEQ + rowA) * DMODEL + h * DHEAD;
    const size_t baseB = baseA + (size_t)8 * DMODEL;
#pragma unroll
    for (int nt = 0; nt < 16; nt++) {
        int d = nt * 8 + 2 * (lane & 3);
        __half2 v0 = __floats2half2_rn(O[nt][0] * inv0, O[nt][1] * inv0);
        __half2 v1 = __floats2half2_rn(O[nt][2] * inv1, O[nt][3] * inv1);
        *reinterpret_cast<__half2*>(O16 + baseA + d) = v0;
        *reinterpret_cast<__half2*>(O16 + baseB + d) = v1;
    }
}

// ---------------------------------------------------------------------------
extern "C" void kernel_launch(void* const* d_in, const int* in_sizes, int n_in,
                              void* d_out, int out_size)
{
    const float* x    = (const float*)d_in[0];
    const float* Wqkv = (const float*)d_in[1];
    const float* WO   = (const float*)d_in[2];
    float* out = (float*)d_out;

    float2* rope;
    cudaGetSymbolAddress((void**)&rope, g_rope);
    __half *x16, *wq16, *a16, *wo16;
    cudaGetSymbolAddress((void**)&x16, g_x16);
    cudaGetSymbolAddress((void**)&wq16, g_wq16);
    cudaGetSymbolAddress((void**)&a16, g_a16);
    cudaGetSymbolAddress((void**)&wo16, g_wo16);
    __half *qh16, *ql16, *kh16, *vh16;
    cudaGetSymbolAddress((void**)&qh16, g_qh16); cudaGetSymbolAddress((void**)&ql16, g_ql16);
    cudaGetSymbolAddress((void**)&kh16, g_kh16); cudaGetSymbolAddress((void**)&vh16, g_vh16);

    cudaFuncSetAttribute(gemm_mma, cudaFuncAttributeMaxDynamicSharedMemorySize, GSMEM);
    cudaFuncSetAttribute(gemm_qkv, cudaFuncAttributeMaxDynamicSharedMemorySize, GSMEM);
    cudaFuncSetAttribute(attn_mma, cudaFuncAttributeMaxDynamicSharedMemorySize, AT_SMEM);

    rope_table_kernel<<<(SEQ * 64) / 256, 256>>>(rope);
    cvt_all_kernel<<<N4_ALL / 256, 256>>>(
        (const float4*)x, (uint2*)x16,
        (const float4*)Wqkv, (uint2*)wq16,
        (const float4*)WO, (uint2*)wo16);

    // 1) QKV GEMM with fused RoPE + fp16 pack + [B,H,T,D] transpose
    {
        dim3 grid(QKVDIM / BN, MROWS / BM);
        gemm_qkv<<<grid, 256, GSMEM>>>(x16, wq16, rope, qh16, ql16, kh16, vh16);
    }

    // 2) flash attention -> fp16 (a16)
    {
        dim3 grid(SEQ / 128, NHEADS, BATCH);
        attn_mma<<<grid, 256, AT_SMEM>>>(qh16, ql16, kh16, vh16, a16);
    }

    // 3) out = att @ WO^T
    {
        dim3 grid(DMODEL / BN, MROWS / BM);
        gemm_mma<<<grid, 256, GSMEM>>>(a16, wo16, out, DMODEL);
    }
}

// round 15
// speedup vs baseline: 1.0347x; 1.0347x over previous
#include <cuda_runtime.h>
#include <cuda_bf16.h>
#include <cuda_fp16.h>
#include <math.h>
#include <stdint.h>

// Problem constants
#define BATCH   2
#define SEQ     2048
#define DMODEL  2048
#define NHEADS  16
#define DHEAD   128
#define MROWS   (BATCH*SEQ)          // 4096
#define QKVDIM  (3*DMODEL)           // 6144
#define KDIM    2048

// Scratch (__device__ globals; allocation-free rule)
__device__ float2 g_rope[(size_t)SEQ * 64];
__device__ __half g_x16[(size_t)MROWS * KDIM];
__device__ __half g_wq16[(size_t)QKVDIM * KDIM];
__device__ __half g_a16[(size_t)MROWS * DMODEL];
__device__ __half g_wo16[(size_t)DMODEL * KDIM];
// fp16 attention operands, [B][H][T][D]
#define NATT ((size_t)BATCH * NHEADS * SEQ * DHEAD)
__device__ __half g_qh16[NATT], g_ql16[NATT];
__device__ __half g_kh16[NATT];
__device__ __half g_vh16[NATT];

// ---------------------------------------------------------------------------
// PTX helpers
// ---------------------------------------------------------------------------
static __device__ __forceinline__ uint32_t smem_u32(const void* p) {
    uint32_t a;
    asm("{ .reg .u64 t; cvta.to.shared.u64 t, %1; cvt.u32.u64 %0, t; }" : "=r"(a) : "l"(p));
    return a;
}
static __device__ __forceinline__ void cpasync16(uint32_t dst, const void* src) {
    asm volatile("cp.async.cg.shared.global [%0], [%1], 16;\n" :: "r"(dst), "l"(src));
}
#define CP_COMMIT() asm volatile("cp.async.commit_group;\n" ::: "memory")
#define CP_WAIT0()  asm volatile("cp.async.wait_group 0;\n" ::: "memory")
#define CP_WAIT1()  asm volatile("cp.async.wait_group 1;\n" ::: "memory")

static __device__ __forceinline__ void ldsm_x4(uint32_t& r0, uint32_t& r1,
                                               uint32_t& r2, uint32_t& r3, uint32_t a) {
    asm volatile("ldmatrix.sync.aligned.m8n8.x4.shared.b16 {%0,%1,%2,%3}, [%4];"
                 : "=r"(r0), "=r"(r1), "=r"(r2), "=r"(r3) : "r"(a));
}
static __device__ __forceinline__ void ldsm_x4t(uint32_t& r0, uint32_t& r1,
                                                uint32_t& r2, uint32_t& r3, uint32_t a) {
    asm volatile("ldmatrix.sync.aligned.m8n8.x4.trans.shared.b16 {%0,%1,%2,%3}, [%4];"
                 : "=r"(r0), "=r"(r1), "=r"(r2), "=r"(r3) : "r"(a));
}
static __device__ __forceinline__ void mma_f16(float* c, const uint32_t* a,
                                               uint32_t b0, uint32_t b1) {
    asm volatile(
        "mma.sync.aligned.m16n8k16.row.col.f32.f16.f16.f32 "
        "{%0,%1,%2,%3}, {%4,%5,%6,%7}, {%8,%9}, {%0,%1,%2,%3};"
        : "+f"(c[0]), "+f"(c[1]), "+f"(c[2]), "+f"(c[3])
        : "r"(a[0]), "r"(a[1]), "r"(a[2]), "r"(a[3]), "r"(b0), "r"(b1));
}
static __device__ __forceinline__ void pack_hl(float f0, float f1, uint32_t& hi, uint32_t& lo) {
    __half2 h = __floats2half2_rn(f0, f1);
    float2 fb = __half22float2(h);
    __half2 l2 = __floats2half2_rn(f0 - fb.x, f1 - fb.y);
    hi = *reinterpret_cast<uint32_t*>(&h);
    lo = *reinterpret_cast<uint32_t*>(&l2);
}
static __device__ __forceinline__ uint32_t ex2_f16x2(float a, float b) {
    uint32_t d;
    asm("{ .reg .b32 t;\n cvt.rn.f16x2.f32 t, %2, %1;\n ex2.approx.f16x2 %0, t;\n}"
        : "=r"(d) : "f"(a), "f"(b));
    return d;
}

// ---------------------------------------------------------------------------
// Merged fp32 -> fp16 conversion for x, Wqkv, WO (one launch)
// ---------------------------------------------------------------------------
#define N4_X  ((MROWS * KDIM) / 4)
#define N4_WQ ((QKVDIM * KDIM) / 4)
#define N4_WO ((DMODEL * KDIM) / 4)
#define N4_ALL (N4_X + N4_WQ + N4_WO)

__global__ __launch_bounds__(256) void cvt_all_kernel(
    const float4* __restrict__ x,  uint2* __restrict__ x16,
    const float4* __restrict__ wq, uint2* __restrict__ wq16,
    const float4* __restrict__ wo, uint2* __restrict__ wo16)
{
    int idx = blockIdx.x * 256 + threadIdx.x;
    const float4* s;
    uint2* d;
    int i;
    if (idx < N4_X)              { s = x;  d = x16;  i = idx; }
    else if (idx < N4_X + N4_WQ) { s = wq; d = wq16; i = idx - N4_X; }
    else                         { s = wo; d = wo16; i = idx - N4_X - N4_WQ; }
    float4 v = s[i];
    __half2 h01 = __floats2half2_rn(v.x, v.y);
    __half2 h23 = __floats2half2_rn(v.z, v.w);
    uint2 dv;
    dv.x = *reinterpret_cast<uint32_t*>(&h01); dv.y = *reinterpret_cast<uint32_t*>(&h23);
    d[i] = dv;
}

// ---------------------------------------------------------------------------
// RoPE cos/sin table
// ---------------------------------------------------------------------------
__global__ __launch_bounds__(256) void rope_table_kernel(float2* __restrict__ tab)
{
    int idx = blockIdx.x * 256 + threadIdx.x;
    int i = idx & 63, t = idx >> 6;
    double freq = exp(-9.210340371976184 * (double)(2 * i) / 128.0);
    double sd, cd;
    sincos((double)t * freq, &sd, &cd);
    tab[idx] = make_float2((float)cd, (float)sd);
}

// ---------------------------------------------------------------------------
// GEMM mainloop (NT, fp16: C = A * B^T), BK=64 double-buffered, occ 2.
// BM=BN=128, 256 threads, 8 warps (2m x 4n), warp tile 64x32.
// ---------------------------------------------------------------------------
#define BM 128
#define BN 128
#define BK 64
#define SROW 72
#define PART_BYTES (128 * SROW * 2)          // 18432
#define A_OFF 0
#define B_OFF PART_BYTES
#define STG_BYTES (2 * PART_BYTES)           // 36864
#define GSMEM (2 * STG_BYTES)                // 73728

static __device__ __forceinline__ void g_load_stage(
    uint32_t sb, int buf, int s, int bm, int bn, int tid,
    const __half* __restrict__ A, const __half* __restrict__ B)
{
    uint32_t base = sb + buf * STG_BYTES;
    const int k0 = s * BK;
#pragma unroll
    for (int it = 0; it < 8; it++) {
        int idx = tid + it * 256;
        int part = idx >> 10;
        int rem = idx & 1023;
        int r = rem >> 3, ch = rem & 7;
        const __half* src = part ? B : A;
        int row = part ? (bn + r) : (bm + r);
        cpasync16(base + part * PART_BYTES + r * (SROW * 2) + ch * 16,
                  src + (size_t)row * KDIM + k0 + ch * 8);
    }
    CP_COMMIT();
}

static __device__ __forceinline__ void g_mainloop(
    uint32_t sb, int bm, int bn, int tid, int lane, int wm, int wn,
    const __half* __restrict__ A, const __half* __restrict__ B,
    float acc[4][4][4])
{
    const uint32_t aRow = wm * 64 + (lane & 15);
    const uint32_t aCol = (lane >> 4) << 3;
    const uint32_t bOff = (wn * 32 + (lane & 7) + ((lane & 16) >> 1)) * (SROW * 2)
                        + (((lane >> 3) & 1) << 3) * 2;

    g_load_stage(sb, 0, 0, bm, bn, tid, A, B);

    const int NS = KDIM / BK;                // 32
    for (int s = 0; s < NS; s++) {
        const int buf = s & 1;
        if (s + 1 < NS) {
            g_load_stage(sb, buf ^ 1, s + 1, bm, bn, tid, A, B);
            CP_WAIT1();
        } else {
            CP_WAIT0();
        }
        __syncthreads();

        uint32_t base = sb + buf * STG_BYTES;
#pragma unroll
        for (int kk = 0; kk < BK; kk += 16) {
            uint32_t af[4][4], bf[4][2];
#pragma unroll
            for (int mt = 0; mt < 4; mt++)
                ldsm_x4(af[mt][0], af[mt][1], af[mt][2], af[mt][3],
                        base + A_OFF + (aRow + mt * 16) * (SROW * 2) + (aCol + kk) * 2);
#pragma unroll
            for (int np = 0; np < 2; np++)
                ldsm_x4(bf[2*np][0], bf[2*np][1], bf[2*np+1][0], bf[2*np+1][1],
                        base + B_OFF + bOff + np * 16 * (SROW * 2) + kk * 2);
#pragma unroll
            for (int mt = 0; mt < 4; mt++)
#pragma unroll
                for (int nt = 0; nt < 4; nt++)
                    mma_f16(acc[mt][nt], af[mt], bf[nt][0], bf[nt][1]);
        }
        __syncthreads();
    }
}

// Plain fp32-output GEMM (WO projection)
__global__ __launch_bounds__(256, 2) void gemm_mma(
    const __half* __restrict__ A, const __half* __restrict__ B,
    float* __restrict__ C, int ldc)
{
    extern __shared__ char smem[];
    uint32_t sb = smem_u32(smem);
    const int tid = threadIdx.x, wid = tid >> 5, lane = tid & 31;
    const int wm = wid >> 2, wn = wid & 3;
    const int bm = blockIdx.y * BM, bn = blockIdx.x * BN;

    float acc[4][4][4];
#pragma unroll
    for (int i = 0; i < 4; i++)
#pragma unroll
        for (int j = 0; j < 4; j++)
#pragma unroll
            for (int e = 0; e < 4; e++) acc[i][j][e] = 0.f;

    g_mainloop(sb, bm, bn, tid, lane, wm, wn, A, B, acc);

    const int r0 = bm + wm * 64 + (lane >> 2);
    const int c0 = bn + wn * 32 + 2 * (lane & 3);
#pragma unroll
    for (int mt = 0; mt < 4; mt++)
#pragma unroll
        for (int nt = 0; nt < 4; nt++) {
            float2 v0 = make_float2(acc[mt][nt][0], acc[mt][nt][1]);
            float2 v1 = make_float2(acc[mt][nt][2], acc[mt][nt][3]);
            *reinterpret_cast<float2*>(&C[(size_t)(r0 + mt * 16)     * ldc + c0 + nt * 8]) = v0;
            *reinterpret_cast<float2*>(&C[(size_t)(r0 + mt * 16 + 8) * ldc + c0 + nt * 8]) = v1;
        }
}

// QKV GEMM with fused RoPE + fp16 pack + [B,H,T,D] transpose epilogue.
__global__ __launch_bounds__(256, 2) void gemm_qkv(
    const __half* __restrict__ A, const __half* __restrict__ B,
    const float2* __restrict__ tab,
    __half* __restrict__ Qh, __half* __restrict__ Ql,
    __half* __restrict__ Kh, __half* __restrict__ Vh)
{
    extern __shared__ char smem[];
    uint32_t sb = smem_u32(smem);
    const int tid = threadIdx.x, wid = tid >> 5, lane = tid & 31;
    const int wm = wid >> 2, wn = wid & 3;
    const int bm = blockIdx.y * BM, bn = blockIdx.x * BN;

    float acc[4][4][4];
#pragma unroll
    for (int i = 0; i < 4; i++)
#pragma unroll
        for (int j = 0; j < 4; j++)
#pragma unroll
            for (int e = 0; e < 4; e++) acc[i][j][e] = 0.f;

    g_mainloop(sb, bm, bn, tid, lane, wm, wn, A, B, acc);

    const int mat  = bn >> 11;                  // 0=Q,1=K,2=V
    const int head = (bn >> 7) & (NHEADS - 1);
    const float QSCL = 0.1275174456f;           // log2(e)/sqrt(128)

    const int r0 = bm + wm * 64 + (lane >> 2);
    const int c0 = (bn & 127) + wn * 32 + 2 * (lane & 3);
    const int b  = r0 >> 11;
    const size_t obase = ((size_t)(b * NHEADS + head)) * SEQ * DHEAD;

#pragma unroll
    for (int mt = 0; mt < 4; mt++) {
        const int tA = (r0 + mt * 16) & (SEQ - 1);
        const int tB = tA + 8;
#pragma unroll
        for (int nt = 0; nt < 4; nt++) {
            const int d = c0 + nt * 8;
            float x0 = acc[mt][nt][0], x1 = acc[mt][nt][1];
            float y0 = acc[mt][nt][2], y1 = acc[mt][nt][3];
            if (mat < 2) {
                float2 csA = tab[tA * 64 + (d >> 1)];
                float2 csB = tab[tB * 64 + (d >> 1)];
                float nx0 = x0 * csA.x - x1 * csA.y;
                float nx1 = x1 * csA.x + x0 * csA.y;
                float ny0 = y0 * csB.x - y1 * csB.y;
                float ny1 = y1 * csB.x + y0 * csB.y;
                x0 = nx0; x1 = nx1; y0 = ny0; y1 = ny1;
                if (mat == 0) { x0 *= QSCL; x1 *= QSCL; y0 *= QSCL; y1 *= QSCL; }
            }
            size_t dA = obase + (size_t)tA * DHEAD + d;
            size_t dB = obase + (size_t)tB * DHEAD + d;
            if (mat == 0) {
                uint32_t hi, lo;
                pack_hl(x0, x1, hi, lo);
                *reinterpret_cast<uint32_t*>(Qh + dA) = hi;
                *reinterpret_cast<uint32_t*>(Ql + dA) = lo;
                pack_hl(y0, y1, hi, lo);
                *reinterpret_cast<uint32_t*>(Qh + dB) = hi;
                *reinterpret_cast<uint32_t*>(Ql + dB) = lo;
            } else {
                __half* D = (mat == 1) ? Kh : Vh;
                __half2 v0 = __floats2half2_rn(x0, x1);
                __half2 v1 = __floats2half2_rn(y0, y1);
                *reinterpret_cast<__half2*>(D + dA) = v0;
                *reinterpret_cast<__half2*>(D + dB) = v1;
            }
        }
    }
}

// ---------------------------------------------------------------------------
// Flash attention. TQ=64, 128 threads (4 warps), 2 CTAs/SM for overlap.
// Q direct global->registers; KV double-buffered 64-key tiles.
// ---------------------------------------------------------------------------
#define AT_SROWB 272
#define SM_K  0
#define SM_V  34816
#define KPART 17408
#define AT_SMEM 69632

static __device__ __forceinline__ void at_load_kv(
    uint32_t sb, int buf, int kt, size_t bh, int tid,
    const __half* __restrict__ Kh, const __half* __restrict__ Vh)
{
    const int k0 = kt * 64;
#pragma unroll
    for (int it = 0; it < 16; it++) {
        int idx = tid + it * 128;           // 0..2047
        int part = idx >> 10;               // 0:Kh 1:Vh
        int rem = idx & 1023;
        int r = rem >> 4, ch = rem & 15;
        const __half* src = (part == 0) ? Kh : Vh;
        uint32_t dbase = ((part == 0) ? SM_K : SM_V) + buf * KPART;
        cpasync16(sb + dbase + r * AT_SROWB + ch * 16,
                  src + ((size_t)(bh + k0 + r)) * DHEAD + ch * 8);
    }
    CP_COMMIT();
}

__global__ __launch_bounds__(128, 2) void attn_mma(
    const __half* __restrict__ Qh, const __half* __restrict__ Ql,
    const __half* __restrict__ Kh, const __half* __restrict__ Vh,
    __half* __restrict__ O16)
{
    extern __shared__ char smem[];
    uint32_t sb = smem_u32(smem);
    const int tid = threadIdx.x, lane = tid & 31, w = tid >> 5;   // w 0..3
    const int qt = gridDim.x - 1 - blockIdx.x;
    const int h = blockIdx.y, b = blockIdx.z;
    const int q0 = qt * 64;
    const size_t bh = (size_t)(b * NHEADS + h) * SEQ;

    at_load_kv(sb, 0, 0, bh, tid, Kh, Vh);

    // Q fragments straight from global into registers.
    uint32_t qhf[8][4], qlf[8][4];
    {
        const size_t rowbase = (bh + q0 + w * 16 + (lane >> 2)) * (size_t)DHEAD
                             + 2 * (lane & 3);
        const __half* ph = Qh + rowbase;
        const __half* pl = Ql + rowbase;
#pragma unroll
        for (int ks = 0; ks < 8; ks++) {
            int c = ks * 16;
            qhf[ks][0] = *reinterpret_cast<const uint32_t*>(ph + c);
            qhf[ks][1] = *reinterpret_cast<const uint32_t*>(ph + 8 * DHEAD + c);
            qhf[ks][2] = *reinterpret_cast<const uint32_t*>(ph + c + 8);
            qhf[ks][3] = *reinterpret_cast<const uint32_t*>(ph + 8 * DHEAD + c + 8);
            qlf[ks][0] = *reinterpret_cast<const uint32_t*>(pl + c);
            qlf[ks][1] = *reinterpret_cast<const uint32_t*>(pl + 8 * DHEAD + c);
            qlf[ks][2] = *reinterpret_cast<const uint32_t*>(pl + c + 8);
            qlf[ks][3] = *reinterpret_cast<const uint32_t*>(pl + 8 * DHEAD + c + 8);
        }
    }

    float m[2] = {-1e30f, -1e30f}, l[2] = {0.f, 0.f};
    float O[16][4];
#pragma unroll
    for (int i = 0; i < 16; i++)
#pragma unroll
        for (int e = 0; e < 4; e++) O[i][e] = 0.f;

    const uint32_t koff = ((lane & 7) + ((lane & 16) >> 1)) * AT_SROWB + (((lane >> 3) & 1) << 3) * 2;
    const uint32_t voff = (lane & 15) * AT_SROWB + (((uint32_t)lane >> 4) << 3) * 2;
    const uint32_t ONES = 0x3C003C00u;

    const int nkt = qt + 1;
    for (int kt = 0; kt < nkt; kt++) {
        const int buf = kt & 1;
        __syncthreads();
        if (kt + 1 < nkt) {
            at_load_kv(sb, buf ^ 1, kt + 1, bh, tid, Kh, Vh);
            CP_WAIT1();
        } else {
            CP_WAIT0();
        }
        __syncthreads();

        // ---- S = Q K^T (2-term: Qh*Kh + Ql*Kh), Q from registers ----
        float sacc[8][4];
#pragma unroll
        for (int nt = 0; nt < 8; nt++)
#pragma unroll
            for (int e = 0; e < 4; e++) sacc[nt][e] = 0.f;

        const uint32_t kbase = sb + SM_K + buf * KPART;
#pragma unroll
        for (int ks = 0; ks < 8; ks++) {
#pragma unroll
            for (int np = 0; np < 4; np++) {
                uint32_t k0r, k1r, k2r, k3r;
                ldsm_x4(k0r, k1r, k2r, k3r,
                        kbase + koff + np * 16 * AT_SROWB + ks * 32);
                mma_f16(sacc[2*np],   qhf[ks], k0r, k1r);
                mma_f16(sacc[2*np],   qlf[ks], k0r, k1r);
                mma_f16(sacc[2*np+1], qhf[ks], k2r, k3r);
                mma_f16(sacc[2*np+1], qlf[ks], k2r, k3r);
            }
        }

        // ---- causal mask (diagonal tiles only) ----
        const int k0 = kt * 64;
        if (k0 + 63 > q0 + w * 16) {
            const int rA = q0 + w * 16 + (lane >> 2);
#pragma unroll
            for (int nt = 0; nt < 8; nt++) {
                int c = k0 + nt * 8 + 2 * (lane & 3);
                if (c     > rA)     sacc[nt][0] = -1e30f;
                if (c + 1 > rA)     sacc[nt][1] = -1e30f;
                if (c     > rA + 8) sacc[nt][2] = -1e30f;
                if (c + 1 > rA + 8) sacc[nt][3] = -1e30f;
            }
        }

        // ---- online softmax (log2 units) ----
        float mx0 = sacc[0][0], mx1 = sacc[0][2];
#pragma unroll
        for (int nt = 0; nt < 8; nt++) {
            mx0 = fmaxf(mx0, fmaxf(sacc[nt][0], sacc[nt][1]));
            mx1 = fmaxf(mx1, fmaxf(sacc[nt][2], sacc[nt][3]));
        }
        mx0 = fmaxf(mx0, __shfl_xor_sync(0xffffffffu, mx0, 1));
        mx0 = fmaxf(mx0, __shfl_xor_sync(0xffffffffu, mx0, 2));
        mx1 = fmaxf(mx1, __shfl_xor_sync(0xffffffffu, mx1, 1));
        mx1 = fmaxf(mx1, __shfl_xor_sync(0xffffffffu, mx1, 2));
        const float mn0 = fmaxf(m[0], mx0), mn1 = fmaxf(m[1], mx1);
        const float fac0 = exp2f(m[0] - mn0), fac1 = exp2f(m[1] - mn1);
        m[0] = mn0; m[1] = mn1;

        // ---- P = 2^(s - mn) as fp16 A-fragments ----
        uint32_t aPh[4][4];
#pragma unroll
        for (int ks = 0; ks < 4; ks++) {
            aPh[ks][0] = ex2_f16x2(sacc[2*ks][0]   - mn0, sacc[2*ks][1]   - mn0);
            aPh[ks][1] = ex2_f16x2(sacc[2*ks][2]   - mn1, sacc[2*ks][3]   - mn1);
            aPh[ks][2] = ex2_f16x2(sacc[2*ks+1][0] - mn0, sacc[2*ks+1][1] - mn0);
            aPh[ks][3] = ex2_f16x2(sacc[2*ks+1][2] - mn1, sacc[2*ks+1][3] - mn1);
        }

        // ---- rescale O; O += P Vh; l via ones-mma ----
#pragma unroll
        for (int i = 0; i < 16; i++) {
            O[i][0] *= fac0; O[i][1] *= fac0;
            O[i][2] *= fac1; O[i][3] *= fac1;
        }
        float Olsum[4] = {0.f, 0.f, 0.f, 0.f};
        const uint32_t vbase = sb + SM_V + buf * KPART;
#pragma unroll
        for (int ks = 0; ks < 4; ks++) {
            mma_f16(Olsum, aPh[ks], ONES, ONES);
#pragma unroll
            for (int dt = 0; dt < 8; dt++) {
                uint32_t va = vbase + voff + ks * 16 * AT_SROWB + dt * 32;
                uint32_t vh0, vh1, vh2, vh3;
                ldsm_x4t(vh0, vh1, vh2, vh3, va);
                mma_f16(O[2*dt],   aPh[ks], vh0, vh1);
                mma_f16(O[2*dt+1], aPh[ks], vh2, vh3);
            }
        }
        l[0] = l[0] * fac0 + Olsum[0];
        l[1] = l[1] * fac1 + Olsum[2];
    }

    // ---- normalize & write fp16 to [b, t, h*128+d] ----
    const float inv0 = 1.f / l[0], inv1 = 1.f / l[1];
    const int rowA = q0 + w * 16 + (lane >> 2);
    const size_t baseA = ((size_t)b * SEQ + rowA) * DMODEL + h * DHEAD;
    const size_t baseB = baseA + (size_t)8 * DMODEL;
#pragma unroll
    for (int nt = 0; nt < 16; nt++) {
        int d = nt * 8 + 2 * (lane & 3);
        __half2 v0 = __floats2half2_rn(O[nt][0] * inv0, O[nt][1] * inv0);
        __half2 v1 = __floats2half2_rn(O[nt][2] * inv1, O[nt][3] * inv1);
        *reinterpret_cast<__half2*>(O16 + baseA + d) = v0;
        *reinterpret_cast<__half2*>(O16 + baseB + d) = v1;
    }
}

// ---------------------------------------------------------------------------
extern "C" void kernel_launch(void* const* d_in, const int* in_sizes, int n_in,
                              void* d_out, int out_size)
{
    const float* x    = (const float*)d_in[0];
    const float* Wqkv = (const float*)d_in[1];
    const float* WO   = (const float*)d_in[2];
    float* out = (float*)d_out;

    float2* rope;
    cudaGetSymbolAddress((void**)&rope, g_rope);
    __half *x16, *wq16, *a16, *wo16;
    cudaGetSymbolAddress((void**)&x16, g_x16);
    cudaGetSymbolAddress((void**)&wq16, g_wq16);
    cudaGetSymbolAddress((void**)&a16, g_a16);
    cudaGetSymbolAddress((void**)&wo16, g_wo16);
    __half *qh16, *ql16, *kh16, *vh16;
    cudaGetSymbolAddress((void**)&qh16, g_qh16); cudaGetSymbolAddress((void**)&ql16, g_ql16);
    cudaGetSymbolAddress((void**)&kh16, g_kh16); cudaGetSymbolAddress((void**)&vh16, g_vh16);

    cudaFuncSetAttribute(gemm_mma, cudaFuncAttributeMaxDynamicSharedMemorySize, GSMEM);
    cudaFuncSetAttribute(gemm_qkv, cudaFuncAttributeMaxDynamicSharedMemorySize, GSMEM);
    cudaFuncSetAttribute(attn_mma, cudaFuncAttributeMaxDynamicSharedMemorySize, AT_SMEM);

    rope_table_kernel<<<(SEQ * 64) / 256, 256>>>(rope);
    cvt_all_kernel<<<N4_ALL / 256, 256>>>(
        (const float4*)x, (uint2*)x16,
        (const float4*)Wqkv, (uint2*)wq16,
        (const float4*)WO, (uint2*)wo16);

    // 1) QKV GEMM with fused RoPE + fp16 pack + [B,H,T,D] transpose
    {
        dim3 grid(QKVDIM / BN, MROWS / BM);
        gemm_qkv<<<grid, 256, GSMEM>>>(x16, wq16, rope, qh16, ql16, kh16, vh16);
    }

    // 2) flash attention -> fp16 (a16), TQ=64 CTAs for occupancy 2
    {
        dim3 grid(SEQ / 64, NHEADS, BATCH);
        attn_mma<<<grid, 128, AT_SMEM>>>(qh16, ql16, kh16, vh16, a16);
    }

    // 3) out = att @ WO^T
    {
        dim3 grid(DMODEL / BN, MROWS / BM);
        gemm_mma<<<grid, 256, GSMEM>>>(a16, wo16, out, DMODEL);
    }
}

// round 17
// speedup vs baseline: 1.1011x; 1.0642x over previous
#include <cuda_runtime.h>
#include <cuda_bf16.h>
#include <cuda_fp16.h>
#include <math.h>
#include <stdint.h>

// Problem constants
#define BATCH   2
#define SEQ     2048
#define DMODEL  2048
#define NHEADS  16
#define DHEAD   128
#define MROWS   (BATCH*SEQ)          // 4096
#define QKVDIM  (3*DMODEL)           // 6144
#define KDIM    2048

// Scratch (__device__ globals; allocation-free rule)
__device__ float2 g_rope[(size_t)SEQ * 64];
__device__ __half g_x16[(size_t)MROWS * KDIM];
__device__ __half g_wq16[(size_t)QKVDIM * KDIM];
__device__ __half g_a16[(size_t)MROWS * DMODEL];
__device__ __half g_wo16[(size_t)DMODEL * KDIM];
// fp16 attention operands, [B][H][T][D]
#define NATT ((size_t)BATCH * NHEADS * SEQ * DHEAD)
__device__ __half g_q16[NATT];
__device__ __half g_kh16[NATT];
__device__ __half g_vh16[NATT];

// ---------------------------------------------------------------------------
// PTX helpers
// ---------------------------------------------------------------------------
static __device__ __forceinline__ uint32_t smem_u32(const void* p) {
    uint32_t a;
    asm("{ .reg .u64 t; cvta.to.shared.u64 t, %1; cvt.u32.u64 %0, t; }" : "=r"(a) : "l"(p));
    return a;
}
static __device__ __forceinline__ void cpasync16(uint32_t dst, const void* src) {
    asm volatile("cp.async.cg.shared.global [%0], [%1], 16;\n" :: "r"(dst), "l"(src));
}
#define CP_COMMIT() asm volatile("cp.async.commit_group;\n" ::: "memory")
#define CP_WAIT0()  asm volatile("cp.async.wait_group 0;\n" ::: "memory")
#define CP_WAIT1()  asm volatile("cp.async.wait_group 1;\n" ::: "memory")

static __device__ __forceinline__ void ldsm_x4(uint32_t& r0, uint32_t& r1,
                                               uint32_t& r2, uint32_t& r3, uint32_t a) {
    asm volatile("ldmatrix.sync.aligned.m8n8.x4.shared.b16 {%0,%1,%2,%3}, [%4];"
                 : "=r"(r0), "=r"(r1), "=r"(r2), "=r"(r3) : "r"(a));
}
static __device__ __forceinline__ void ldsm_x4t(uint32_t& r0, uint32_t& r1,
                                                uint32_t& r2, uint32_t& r3, uint32_t a) {
    asm volatile("ldmatrix.sync.aligned.m8n8.x4.trans.shared.b16 {%0,%1,%2,%3}, [%4];"
                 : "=r"(r0), "=r"(r1), "=r"(r2), "=r"(r3) : "r"(a));
}
static __device__ __forceinline__ void mma_f16(float* c, const uint32_t* a,
                                               uint32_t b0, uint32_t b1) {
    asm volatile(
        "mma.sync.aligned.m16n8k16.row.col.f32.f16.f16.f32 "
        "{%0,%1,%2,%3}, {%4,%5,%6,%7}, {%8,%9}, {%0,%1,%2,%3};"
        : "+f"(c[0]), "+f"(c[1]), "+f"(c[2]), "+f"(c[3])
        : "r"(a[0]), "r"(a[1]), "r"(a[2]), "r"(a[3]), "r"(b0), "r"(b1));
}
static __device__ __forceinline__ uint32_t ex2_f16x2(float a, float b) {
    uint32_t d;
    asm("{ .reg .b32 t;\n cvt.rn.f16x2.f32 t, %2, %1;\n ex2.approx.f16x2 %0, t;\n}"
        : "=r"(d) : "f"(a), "f"(b));
    return d;
}

// ---------------------------------------------------------------------------
// Merged fp32 -> fp16 conversion for x, Wqkv, WO (one launch)
// ---------------------------------------------------------------------------
#define N4_X  ((MROWS * KDIM) / 4)
#define N4_WQ ((QKVDIM * KDIM) / 4)
#define N4_WO ((DMODEL * KDIM) / 4)
#define N4_ALL (N4_X + N4_WQ + N4_WO)

__global__ __launch_bounds__(256) void cvt_all_kernel(
    const float4* __restrict__ x,  uint2* __restrict__ x16,
    const float4* __restrict__ wq, uint2* __restrict__ wq16,
    const float4* __restrict__ wo, uint2* __restrict__ wo16)
{
    int idx = blockIdx.x * 256 + threadIdx.x;
    const float4* s;
    uint2* d;
    int i;
    if (idx < N4_X)              { s = x;  d = x16;  i = idx; }
    else if (idx < N4_X + N4_WQ) { s = wq; d = wq16; i = idx - N4_X; }
    else                         { s = wo; d = wo16; i = idx - N4_X - N4_WQ; }
    float4 v = s[i];
    __half2 h01 = __floats2half2_rn(v.x, v.y);
    __half2 h23 = __floats2half2_rn(v.z, v.w);
    uint2 dv;
    dv.x = *reinterpret_cast<uint32_t*>(&h01); dv.y = *reinterpret_cast<uint32_t*>(&h23);
    d[i] = dv;
}

// ---------------------------------------------------------------------------
// RoPE cos/sin table
// ---------------------------------------------------------------------------
__global__ __launch_bounds__(256) void rope_table_kernel(float2* __restrict__ tab)
{
    int idx = blockIdx.x * 256 + threadIdx.x;
    int i = idx & 63, t = idx >> 6;
    double freq = exp(-9.210340371976184 * (double)(2 * i) / 128.0);
    double sd, cd;
    sincos((double)t * freq, &sd, &cd);
    tab[idx] = make_float2((float)cd, (float)sd);
}

// ---------------------------------------------------------------------------
// GEMM mainloop (NT, fp16: C = A * B^T), BK=64 double-buffered, occ 2.
// BM=BN=128, 256 threads, 8 warps (2m x 4n), warp tile 64x32.
// ---------------------------------------------------------------------------
#define BM 128
#define BN 128
#define BK 64
#define SROW 72
#define PART_BYTES (128 * SROW * 2)          // 18432
#define A_OFF 0
#define B_OFF PART_BYTES
#define STG_BYTES (2 * PART_BYTES)           // 36864
#define GSMEM (2 * STG_BYTES)                // 73728

static __device__ __forceinline__ void g_load_stage(
    uint32_t sb, int buf, int s, int bm, int bn, int tid,
    const __half* __restrict__ A, const __half* __restrict__ B)
{
    uint32_t base = sb + buf * STG_BYTES;
    const int k0 = s * BK;
#pragma unroll
    for (int it = 0; it < 8; it++) {
        int idx = tid + it * 256;
        int part = idx >> 10;
        int rem = idx & 1023;
        int r = rem >> 3, ch = rem & 7;
        const __half* src = part ? B : A;
        int row = part ? (bn + r) : (bm + r);
        cpasync16(base + part * PART_BYTES + r * (SROW * 2) + ch * 16,
                  src + (size_t)row * KDIM + k0 + ch * 8);
    }
    CP_COMMIT();
}

static __device__ __forceinline__ void g_mainloop(
    uint32_t sb, int bm, int bn, int tid, int lane, int wm, int wn,
    const __half* __restrict__ A, const __half* __restrict__ B,
    float acc[4][4][4])
{
    const uint32_t aRow = wm * 64 + (lane & 15);
    const uint32_t aCol = (lane >> 4) << 3;
    const uint32_t bOff = (wn * 32 + (lane & 7) + ((lane & 16) >> 1)) * (SROW * 2)
                        + (((lane >> 3) & 1) << 3) * 2;

    g_load_stage(sb, 0, 0, bm, bn, tid, A, B);

    const int NS = KDIM / BK;                // 32
    for (int s = 0; s < NS; s++) {
        const int buf = s & 1;
        if (s + 1 < NS) {
            g_load_stage(sb, buf ^ 1, s + 1, bm, bn, tid, A, B);
            CP_WAIT1();
        } else {
            CP_WAIT0();
        }
        __syncthreads();

        uint32_t base = sb + buf * STG_BYTES;
#pragma unroll
        for (int kk = 0; kk < BK; kk += 16) {
            uint32_t af[4][4], bf[4][2];
#pragma unroll
            for (int mt = 0; mt < 4; mt++)
                ldsm_x4(af[mt][0], af[mt][1], af[mt][2], af[mt][3],
                        base + A_OFF + (aRow + mt * 16) * (SROW * 2) + (aCol + kk) * 2);
#pragma unroll
            for (int np = 0; np < 2; np++)
                ldsm_x4(bf[2*np][0], bf[2*np][1], bf[2*np+1][0], bf[2*np+1][1],
                        base + B_OFF + bOff + np * 16 * (SROW * 2) + kk * 2);
#pragma unroll
            for (int mt = 0; mt < 4; mt++)
#pragma unroll
                for (int nt = 0; nt < 4; nt++)
                    mma_f16(acc[mt][nt], af[mt], bf[nt][0], bf[nt][1]);
        }
        __syncthreads();
    }
}

// Plain fp32-output GEMM (WO projection)
__global__ __launch_bounds__(256, 2) void gemm_mma(
    const __half* __restrict__ A, const __half* __restrict__ B,
    float* __restrict__ C, int ldc)
{
    extern __shared__ char smem[];
    uint32_t sb = smem_u32(smem);
    const int tid = threadIdx.x, wid = tid >> 5, lane = tid & 31;
    const int wm = wid >> 2, wn = wid & 3;
    const int bm = blockIdx.y * BM, bn = blockIdx.x * BN;

    float acc[4][4][4];
#pragma unroll
    for (int i = 0; i < 4; i++)
#pragma unroll
        for (int j = 0; j < 4; j++)
#pragma unroll
            for (int e = 0; e < 4; e++) acc[i][j][e] = 0.f;

    g_mainloop(sb, bm, bn, tid, lane, wm, wn, A, B, acc);

    const int r0 = bm + wm * 64 + (lane >> 2);
    const int c0 = bn + wn * 32 + 2 * (lane & 3);
#pragma unroll
    for (int mt = 0; mt < 4; mt++)
#pragma unroll
        for (int nt = 0; nt < 4; nt++) {
            float2 v0 = make_float2(acc[mt][nt][0], acc[mt][nt][1]);
            float2 v1 = make_float2(acc[mt][nt][2], acc[mt][nt][3]);
            *reinterpret_cast<float2*>(&C[(size_t)(r0 + mt * 16)     * ldc + c0 + nt * 8]) = v0;
            *reinterpret_cast<float2*>(&C[(size_t)(r0 + mt * 16 + 8) * ldc + c0 + nt * 8]) = v1;
        }
}

// QKV GEMM with fused RoPE + fp16 pack + [B,H,T,D] transpose epilogue.
// All of Q, K, V now single fp16.
__global__ __launch_bounds__(256, 2) void gemm_qkv(
    const __half* __restrict__ A, const __half* __restrict__ B,
    const float2* __restrict__ tab,
    __half* __restrict__ Q16, __half* __restrict__ Kh, __half* __restrict__ Vh)
{
    extern __shared__ char smem[];
    uint32_t sb = smem_u32(smem);
    const int tid = threadIdx.x, wid = tid >> 5, lane = tid & 31;
    const int wm = wid >> 2, wn = wid & 3;
    const int bm = blockIdx.y * BM, bn = blockIdx.x * BN;

    float acc[4][4][4];
#pragma unroll
    for (int i = 0; i < 4; i++)
#pragma unroll
        for (int j = 0; j < 4; j++)
#pragma unroll
            for (int e = 0; e < 4; e++) acc[i][j][e] = 0.f;

    g_mainloop(sb, bm, bn, tid, lane, wm, wn, A, B, acc);

    const int mat  = bn >> 11;                  // 0=Q,1=K,2=V
    const int head = (bn >> 7) & (NHEADS - 1);
    const float QSCL = 0.1275174456f;           // log2(e)/sqrt(128)

    const int r0 = bm + wm * 64 + (lane >> 2);
    const int c0 = (bn & 127) + wn * 32 + 2 * (lane & 3);
    const int b  = r0 >> 11;
    const size_t obase = ((size_t)(b * NHEADS + head)) * SEQ * DHEAD;
    __half* D = (mat == 0) ? Q16 : (mat == 1) ? Kh : Vh;

#pragma unroll
    for (int mt = 0; mt < 4; mt++) {
        const int tA = (r0 + mt * 16) & (SEQ - 1);
        const int tB = tA + 8;
#pragma unroll
        for (int nt = 0; nt < 4; nt++) {
            const int d = c0 + nt * 8;
            float x0 = acc[mt][nt][0], x1 = acc[mt][nt][1];
            float y0 = acc[mt][nt][2], y1 = acc[mt][nt][3];
            if (mat < 2) {
                float2 csA = tab[tA * 64 + (d >> 1)];
                float2 csB = tab[tB * 64 + (d >> 1)];
                float nx0 = x0 * csA.x - x1 * csA.y;
                float nx1 = x1 * csA.x + x0 * csA.y;
                float ny0 = y0 * csB.x - y1 * csB.y;
                float ny1 = y1 * csB.x + y0 * csB.y;
                x0 = nx0; x1 = nx1; y0 = ny0; y1 = ny1;
                if (mat == 0) { x0 *= QSCL; x1 *= QSCL; y0 *= QSCL; y1 *= QSCL; }
            }
            size_t dA = obase + (size_t)tA * DHEAD + d;
            size_t dB = obase + (size_t)tB * DHEAD + d;
            __half2 v0 = __floats2half2_rn(x0, x1);
            __half2 v1 = __floats2half2_rn(y0, y1);
            *reinterpret_cast<__half2*>(D + dA) = v0;
            *reinterpret_cast<__half2*>(D + dB) = v1;
        }
    }
}

// ---------------------------------------------------------------------------
// Flash attention. TQ=64, 128 threads (4 warps), occ 2. Single-fp16 Q/K/V.
// Q direct global->registers; KV double-buffered 64-key tiles.
// ---------------------------------------------------------------------------
#define AT_SROWB 272
#define SM_K  0
#define SM_V  34816
#define KPART 17408
#define AT_SMEM 69632

static __device__ __forceinline__ void at_load_kv(
    uint32_t sb, int buf, int kt, size_t bh, int tid,
    const __half* __restrict__ Kh, const __half* __restrict__ Vh)
{
    const int k0 = kt * 64;
#pragma unroll
    for (int it = 0; it < 16; it++) {
        int idx = tid + it * 128;
        int part = idx >> 10;               // 0:Kh 1:Vh
        int rem = idx & 1023;
        int r = rem >> 4, ch = rem & 15;
        const __half* src = (part == 0) ? Kh : Vh;
        uint32_t dbase = ((part == 0) ? SM_K : SM_V) + buf * KPART;
        cpasync16(sb + dbase + r * AT_SROWB + ch * 16,
                  src + ((size_t)(bh + k0 + r)) * DHEAD + ch * 8);
    }
    CP_COMMIT();
}

__global__ __launch_bounds__(128, 2) void attn_mma(
    const __half* __restrict__ Q16,
    const __half* __restrict__ Kh, const __half* __restrict__ Vh,
    __half* __restrict__ O16)
{
    extern __shared__ char smem[];
    uint32_t sb = smem_u32(smem);
    const int tid = threadIdx.x, lane = tid & 31, w = tid >> 5;   // w 0..3
    const int qt = gridDim.x - 1 - blockIdx.x;
    const int h = blockIdx.y, b = blockIdx.z;
    const int q0 = qt * 64;
    const size_t bh = (size_t)(b * NHEADS + h) * SEQ;

    at_load_kv(sb, 0, 0, bh, tid, Kh, Vh);

    // Q fragments straight from global into registers.
    uint32_t qf[8][4];
    {
        const size_t rowbase = (bh + q0 + w * 16 + (lane >> 2)) * (size_t)DHEAD
                             + 2 * (lane & 3);
        const __half* pq = Q16 + rowbase;
#pragma unroll
        for (int ks = 0; ks < 8; ks++) {
            int c = ks * 16;
            qf[ks][0] = *reinterpret_cast<const uint32_t*>(pq + c);
            qf[ks][1] = *reinterpret_cast<const uint32_t*>(pq + 8 * DHEAD + c);
            qf[ks][2] = *reinterpret_cast<const uint32_t*>(pq + c + 8);
            qf[ks][3] = *reinterpret_cast<const uint32_t*>(pq + 8 * DHEAD + c + 8);
        }
    }

    float m[2] = {-1e30f, -1e30f}, l[2] = {0.f, 0.f};
    float O[16][4];
#pragma unroll
    for (int i = 0; i < 16; i++)
#pragma unroll
        for (int e = 0; e < 4; e++) O[i][e] = 0.f;

    const uint32_t koff = ((lane & 7) + ((lane & 16) >> 1)) * AT_SROWB + (((lane >> 3) & 1) << 3) * 2;
    const uint32_t voff = (lane & 15) * AT_SROWB + (((uint32_t)lane >> 4) << 3) * 2;
    const uint32_t ONES = 0x3C003C00u;

    const int nkt = qt + 1;
    for (int kt = 0; kt < nkt; kt++) {
        const int buf = kt & 1;
        __syncthreads();
        if (kt + 1 < nkt) {
            at_load_kv(sb, buf ^ 1, kt + 1, bh, tid, Kh, Vh);
            CP_WAIT1();
        } else {
            CP_WAIT0();
        }
        __syncthreads();

        // ---- S = Q K^T (single-term), Q from registers ----
        float sacc[8][4];
#pragma unroll
        for (int nt = 0; nt < 8; nt++)
#pragma unroll
            for (int e = 0; e < 4; e++) sacc[nt][e] = 0.f;

        const uint32_t kbase = sb + SM_K + buf * KPART;
#pragma unroll
        for (int ks = 0; ks < 8; ks++) {
#pragma unroll
            for (int np = 0; np < 4; np++) {
                uint32_t k0r, k1r, k2r, k3r;
                ldsm_x4(k0r, k1r, k2r, k3r,
                        kbase + koff + np * 16 * AT_SROWB + ks * 32);
                mma_f16(sacc[2*np],   qf[ks], k0r, k1r);
                mma_f16(sacc[2*np+1], qf[ks], k2r, k3r);
            }
        }

        // ---- causal mask (diagonal tiles only) ----
        const int k0 = kt * 64;
        if (k0 + 63 > q0 + w * 16) {
            const int rA = q0 + w * 16 + (lane >> 2);
#pragma unroll
            for (int nt = 0; nt < 8; nt++) {
                int c = k0 + nt * 8 + 2 * (lane & 3);
                if (c     > rA)     sacc[nt][0] = -1e30f;
                if (c + 1 > rA)     sacc[nt][1] = -1e30f;
                if (c     > rA + 8) sacc[nt][2] = -1e30f;
                if (c + 1 > rA + 8) sacc[nt][3] = -1e30f;
            }
        }

        // ---- online softmax (log2 units) ----
        float mx0 = sacc[0][0], mx1 = sacc[0][2];
#pragma unroll
        for (int nt = 0; nt < 8; nt++) {
            mx0 = fmaxf(mx0, fmaxf(sacc[nt][0], sacc[nt][1]));
            mx1 = fmaxf(mx1, fmaxf(sacc[nt][2], sacc[nt][3]));
        }
        mx0 = fmaxf(mx0, __shfl_xor_sync(0xffffffffu, mx0, 1));
        mx0 = fmaxf(mx0, __shfl_xor_sync(0xffffffffu, mx0, 2));
        mx1 = fmaxf(mx1, __shfl_xor_sync(0xffffffffu, mx1, 1));
        mx1 = fmaxf(mx1, __shfl_xor_sync(0xffffffffu, mx1, 2));
        const float mn0 = fmaxf(m[0], mx0), mn1 = fmaxf(m[1], mx1);
        const float fac0 = exp2f(m[0] - mn0), fac1 = exp2f(m[1] - mn1);
        m[0] = mn0; m[1] = mn1;

        // ---- P = 2^(s - mn) as fp16 A-fragments ----
        uint32_t aPh[4][4];
#pragma unroll
        for (int ks = 0; ks < 4; ks++) {
            aPh[ks][0] = ex2_f16x2(sacc[2*ks][0]   - mn0, sacc[2*ks][1]   - mn0);
            aPh[ks][1] = ex2_f16x2(sacc[2*ks][2]   - mn1, sacc[2*ks][3]   - mn1);
            aPh[ks][2] = ex2_f16x2(sacc[2*ks+1][0] - mn0, sacc[2*ks+1][1] - mn0);
            aPh[ks][3] = ex2_f16x2(sacc[2*ks+1][2] - mn1, sacc[2*ks+1][3] - mn1);
        }

        // ---- rescale O; O += P Vh; l via ones-mma ----
#pragma unroll
        for (int i = 0; i < 16; i++) {
            O[i][0] *= fac0; O[i][1] *= fac0;
            O[i][2] *= fac1; O[i][3] *= fac1;
        }
        float Olsum[4] = {0.f, 0.f, 0.f, 0.f};
        const uint32_t vbase = sb + SM_V + buf * KPART;
#pragma unroll
        for (int ks = 0; ks < 4; ks++) {
            mma_f16(Olsum, aPh[ks], ONES, ONES);
#pragma unroll
            for (int dt = 0; dt < 8; dt++) {
                uint32_t va = vbase + voff + ks * 16 * AT_SROWB + dt * 32;
                uint32_t vh0, vh1, vh2, vh3;
                ldsm_x4t(vh0, vh1, vh2, vh3, va);
                mma_f16(O[2*dt],   aPh[ks], vh0, vh1);
                mma_f16(O[2*dt+1], aPh[ks], vh2, vh3);
            }
        }
        l[0] = l[0] * fac0 + Olsum[0];
        l[1] = l[1] * fac1 + Olsum[2];
    }

    // ---- normalize & write fp16 to [b, t, h*128+d] ----
    const float inv0 = 1.f / l[0], inv1 = 1.f / l[1];
    const int rowA = q0 + w * 16 + (lane >> 2);
    const size_t baseA = ((size_t)b * SEQ + rowA) * DMODEL + h * DHEAD;
    const size_t baseB = baseA + (size_t)8 * DMODEL;
#pragma unroll
    for (int nt = 0; nt < 16; nt++) {
        int d = nt * 8 + 2 * (lane & 3);
        __half2 v0 = __floats2half2_rn(O[nt][0] * inv0, O[nt][1] * inv0);
        __half2 v1 = __floats2half2_rn(O[nt][2] * inv1, O[nt][3] * inv1);
        *reinterpret_cast<__half2*>(O16 + baseA + d) = v0;
        *reinterpret_cast<__half2*>(O16 + baseB + d) = v1;
    }
}

// ---------------------------------------------------------------------------
extern "C" void kernel_launch(void* const* d_in, const int* in_sizes, int n_in,
                              void* d_out, int out_size)
{
    const float* x    = (const float*)d_in[0];
    const float* Wqkv = (const float*)d_in[1];
    const float* WO   = (const float*)d_in[2];
    float* out = (float*)d_out;

    float2* rope;
    cudaGetSymbolAddress((void**)&rope, g_rope);
    __half *x16, *wq16, *a16, *wo16;
    cudaGetSymbolAddress((void**)&x16, g_x16);
    cudaGetSymbolAddress((void**)&wq16, g_wq16);
    cudaGetSymbolAddress((void**)&a16, g_a16);
    cudaGetSymbolAddress((void**)&wo16, g_wo16);
    __half *q16, *kh16, *vh16;
    cudaGetSymbolAddress((void**)&q16, g_q16);
    cudaGetSymbolAddress((void**)&kh16, g_kh16);
    cudaGetSymbolAddress((void**)&vh16, g_vh16);

    cudaFuncSetAttribute(gemm_mma, cudaFuncAttributeMaxDynamicSharedMemorySize, GSMEM);
    cudaFuncSetAttribute(gemm_qkv, cudaFuncAttributeMaxDynamicSharedMemorySize, GSMEM);
    cudaFuncSetAttribute(attn_mma, cudaFuncAttributeMaxDynamicSharedMemorySize, AT_SMEM);

    rope_table_kernel<<<(SEQ * 64) / 256, 256>>>(rope);
    cvt_all_kernel<<<N4_ALL / 256, 256>>>(
        (const float4*)x, (uint2*)x16,
        (const float4*)Wqkv, (uint2*)wq16,
        (const float4*)WO, (uint2*)wo16);

    // 1) QKV GEMM with fused RoPE + fp16 pack + [B,H,T,D] transpose
    {
        dim3 grid(QKVDIM / BN, MROWS / BM);
        gemm_qkv<<<grid, 256, GSMEM>>>(x16, wq16, rope, q16, kh16, vh16);
    }

    // 2) flash attention -> fp16 (a16), TQ=64 CTAs, occ 2
    {
        dim3 grid(SEQ / 64, NHEADS, BATCH);
        attn_mma<<<grid, 128, AT_SMEM>>>(q16, kh16, vh16, a16);
    }

    // 3) out = att @ WO^T
    {
        dim3 grid(DMODEL / BN, MROWS / BM);
        gemm_mma<<<grid, 256, GSMEM>>>(a16, wo16, out, DMODEL);
    }
}